// round 15
// baseline (speedup 1.0000x reference)
#include <cuda_runtime.h>
#include <cuda_fp16.h>
#include <cstdint>

#define BB 16
#define NN 4096

// ---------------- scratch (device globals; no dynamic allocation) ----------
// g_adjh tiled: [b][mtile 32][kchunk 64] 16KB blocks, SW128-swizzled rows
// g_z*  tiled:  [b][kchunk 64] 8KB blocks (64 d x 64 m), same swizzle
__device__ float g_dis[BB * NN];
__device__ __align__(128) __half g_adjh[(size_t)BB * NN * NN];   // 512 MB
__device__ __align__(128) __half g_z1[(size_t)BB * 64 * NN];     // 8 MB
__device__ __align__(128) __half g_z2[(size_t)BB * 64 * NN];     // 8 MB
__device__ float g_pool[BB * 32 * 128];
__device__ unsigned g_qc, g_q1, g_q2;                 // work queues
__device__ unsigned g_convDone[BB], g_g1Done[BB];     // readiness counters

// ---------------- PTX helpers ------------------------------------------------
__device__ __forceinline__ void ldm4(uint32_t& r0, uint32_t& r1, uint32_t& r2,
                                     uint32_t& r3, uint32_t a) {
    asm volatile("ldmatrix.sync.aligned.m8n8.x4.shared.b16 {%0,%1,%2,%3}, [%4];"
                 : "=r"(r0), "=r"(r1), "=r"(r2), "=r"(r3) : "r"(a));
}
__device__ __forceinline__ void mma16816(float* d, const uint32_t* a, const uint32_t* b) {
    asm volatile(
        "mma.sync.aligned.m16n8k16.row.col.f32.f16.f16.f32 "
        "{%0,%1,%2,%3},{%4,%5,%6,%7},{%8,%9},{%0,%1,%2,%3};"
        : "+f"(d[0]), "+f"(d[1]), "+f"(d[2]), "+f"(d[3])
        : "r"(a[0]), "r"(a[1]), "r"(a[2]), "r"(a[3]), "r"(b[0]), "r"(b[1]));
}
__device__ __forceinline__ void mbar_init(uint32_t a, uint32_t cnt) {
    asm volatile("mbarrier.init.shared.b64 [%0], %1;" :: "r"(a), "r"(cnt) : "memory");
}
__device__ __forceinline__ void mbar_expect(uint32_t a, uint32_t bytes) {
    asm volatile("mbarrier.arrive.expect_tx.shared.b64 _, [%0], %1;"
                 :: "r"(a), "r"(bytes) : "memory");
}
__device__ __forceinline__ void bulk_g2s(uint32_t dst, const void* src,
                                         uint32_t bytes, uint32_t mbar) {
    asm volatile("cp.async.bulk.shared::cluster.global.mbarrier::complete_tx::bytes "
                 "[%0], [%1], %2, [%3];"
                 :: "r"(dst), "l"(src), "r"(bytes), "r"(mbar) : "memory");
}
__device__ __forceinline__ void mbar_wait(uint32_t a, uint32_t parity) {
    asm volatile(
        "{\n\t.reg .pred P;\n"
        "WL%=:\n\t"
        "mbarrier.try_wait.parity.acquire.cta.shared::cta.b64 P, [%0], %1;\n\t"
        "@P bra WD%=;\n\t"
        "bra WL%=;\n"
        "WD%=:\n\t}"
        :: "r"(a), "r"(parity) : "memory");
}

__device__ __forceinline__ void load_wT(const float* __restrict__ W, char* wsPtr, int tid) {
    for (int idx = tid; idx < 4096; idx += 256) {
        int d = idx & 63, k = idx >> 6;
        int chunk = k >> 3;
        int off = d * 128 + ((chunk ^ (d & 7)) << 4) + (k & 7) * 2;
        *(__half*)(wsPtr + off) = __float2half(W[k * 64 + d]);
    }
}

// mini MMA: [128x64 fp16 smem @xsA] x [64x64 W^T @wsA] -> zs[d][m] (pad 136)
__device__ __forceinline__ void mini_mma_store(uint32_t xsA, uint32_t wsA,
                                               __half* zs, int wm, int wn, int lane) {
    float acc[2][4][4];
#pragma unroll
    for (int mt = 0; mt < 2; mt++)
#pragma unroll
        for (int nt = 0; nt < 4; nt++)
#pragma unroll
            for (int c = 0; c < 4; c++) acc[mt][nt][c] = 0.f;
#pragma unroll
    for (int kt = 0; kt < 4; kt++) {
        uint32_t a[2][4], bb[4][2];
        int chunk = kt * 2 + (lane >> 4);
#pragma unroll
        for (int mt = 0; mt < 2; mt++) {
            int row = wm * 32 + mt * 16 + (lane & 15);
            ldm4(a[mt][0], a[mt][1], a[mt][2], a[mt][3],
                 xsA + row * 128 + ((chunk ^ (row & 7)) << 4));
        }
#pragma unroll
        for (int pr = 0; pr < 2; pr++) {
            int rn = wn * 32 + pr * 16 + (lane & 15);
            uint32_t r0, r1, r2, r3;
            ldm4(r0, r1, r2, r3, wsA + rn * 128 + ((chunk ^ (rn & 7)) << 4));
            bb[pr * 2][0] = r0; bb[pr * 2 + 1][0] = r1;
            bb[pr * 2][1] = r2; bb[pr * 2 + 1][1] = r3;
        }
#pragma unroll
        for (int mt = 0; mt < 2; mt++)
#pragma unroll
            for (int nt = 0; nt < 4; nt++) mma16816(acc[mt][nt], a[mt], bb[nt]);
    }
    int g = lane >> 2, t4 = lane & 3;
#pragma unroll
    for (int mt = 0; mt < 2; mt++)
#pragma unroll
        for (int nt = 0; nt < 4; nt++)
#pragma unroll
            for (int h2 = 0; h2 < 2; h2++) {
                int row = wm * 32 + mt * 16 + g + h2 * 8;
                int col = wn * 32 + nt * 8 + t4 * 2;
                zs[(size_t)col * 136 + row]       = __float2half(acc[mt][nt][h2 * 2]);
                zs[(size_t)(col + 1) * 136 + row] = __float2half(acc[mt][nt][h2 * 2 + 1]);
            }
}

__device__ __forceinline__ void store_z_tiled(__half* zbase, int b, int d, int m,
                                              uint32_t v) {
    int kc = m >> 6, ml = m & 63, c = ml >> 3;
    size_t off = ((size_t)(b * 64 + kc)) * 8192 + d * 128 + ((c ^ (d & 7)) << 4) + (ml & 7) * 2;
    *reinterpret_cast<uint32_t*>(reinterpret_cast<char*>(zbase) + off) = v;
}

// ---------------- conv subtask: 64 rows deg+dis+adjh + z1 slice -------------
__device__ void do_conv(unsigned task, const float* __restrict__ adj,
                        const int* __restrict__ ntypes, const int* __restrict__ nlabels,
                        const float* __restrict__ te, const float* __restrict__ le,
                        const float* __restrict__ W1, char* sm, int tid) {
    float* s_dis = (float*)(sm + 48128);   // 64 floats
    float* s_red = (float*)(sm + 48384);   // 8 floats
    float* s_bc  = (float*)(sm + 48416);   // 2 floats
    int b = task >> 6, sub = task & 63;
    int mt = sub >> 1, rbase = (sub & 1) * 64;
    size_t node0 = (size_t)b * NN + sub * 64;
    char* blockBase = reinterpret_cast<char*>(g_adjh) +
                      ((size_t)(b * 32 + mt)) * 64 * 16384;
    int half = tid >> 7, u = tid & 127;

    for (int rr = 0; rr < 32; rr++) {
        int rl = rr * 2 + half;
        const float4* p = reinterpret_cast<const float4*>(adj + (node0 + rl) * NN);
        float4 v[8];
#pragma unroll
        for (int i = 0; i < 8; i++) v[i] = __ldcs(p + u + i * 128);
        float s = 0.f;
#pragma unroll
        for (int i = 0; i < 8; i++) s += (v[i].x + v[i].y) + (v[i].z + v[i].w);
#pragma unroll
        for (int o = 16; o; o >>= 1) s += __shfl_xor_sync(0xffffffffu, s, o);
        if ((u & 31) == 0) s_red[half * 4 + (u >> 5)] = s;
        __syncthreads();
        if (u == 0) {
            float tot = s_red[half * 4] + s_red[half * 4 + 1] +
                        s_red[half * 4 + 2] + s_red[half * 4 + 3];
            float dis = rsqrtf(fmaxf(tot, 1.0f));
            g_dis[node0 + rl] = dis;
            s_dis[rl] = dis;
            s_bc[half] = dis;
        }
        __syncthreads();
        float d = s_bc[half];
        int r = rbase + rl;
#pragma unroll
        for (int i = 0; i < 8; i++) {
            __half2 lo = __floats2half2_rn(v[i].x * d, v[i].y * d);
            __half2 hi = __floats2half2_rn(v[i].z * d, v[i].w * d);
            uint2 o;
            o.x = *reinterpret_cast<uint32_t*>(&lo);
            o.y = *reinterpret_cast<uint32_t*>(&hi);
            int k0 = 4 * (u + i * 128);
            int kc = k0 >> 6, c = (k0 & 63) >> 3;
            size_t off = (size_t)kc * 16384 + r * 128 + ((c ^ (r & 7)) << 4) + (k0 & 7) * 2;
            __stcs(reinterpret_cast<uint2*>(blockBase + off), o);
        }
        __syncthreads();
    }

    // z1 for these 64 nodes (xs rows 64-127 stale; outputs unused)
    load_wT(W1, sm + 16384, tid);
    int node_l = tid >> 1, he = tid & 1;
    if (node_l < 64) {
        size_t node = node0 + node_l;
        const float* src = he ? (le + nlabels[node] * 32) : (te + ntypes[node] * 32);
        float dv = s_dis[node_l];
#pragma unroll
        for (int j = 0; j < 8; j++) {
            float4 v = reinterpret_cast<const float4*>(src)[j];
            __half2 p0 = __floats2half2_rn(v.x * dv, v.y * dv);
            __half2 p1 = __floats2half2_rn(v.z * dv, v.w * dv);
            int col = he * 32 + j * 4, chunk = col >> 3;
            int off = node_l * 128 + ((chunk ^ (node_l & 7)) << 4) + (col & 7) * 2;
            uint2 uu;
            uu.x = *reinterpret_cast<uint32_t*>(&p0);
            uu.y = *reinterpret_cast<uint32_t*>(&p1);
            *reinterpret_cast<uint2*>(sm + off) = uu;
        }
    }
    __syncthreads();
    int warp = tid >> 5, lane = tid & 31;
    uint32_t sA = (uint32_t)__cvta_generic_to_shared(sm);
    __half* zs = reinterpret_cast<__half*>(sm + 24576);
    mini_mma_store(sA, sA + 16384, zs, warp >> 1, warp & 1, lane);
    __syncthreads();
    int m0 = sub * 64;
    for (int idx = tid; idx < 2048; idx += 256) {
        int d = idx >> 5, cw = idx & 31;
        uint32_t v = *reinterpret_cast<uint32_t*>(zs + d * 136 + cw * 2);
        store_z_tiled(g_z1, b, d, m0 + cw * 2, v);
    }
    __syncthreads();
    __threadfence();
    if (tid == 0) atomicAdd(&g_convDone[b], 1u);
}

// ---------------- GEMM task (R9 mainloop + epilogues) ------------------------
__device__ void do_gemm(int mode, int b, int mt,
                        const float* __restrict__ bias, const float* __restrict__ Wnext,
                        char* sm, int tid, uint32_t mF) {
    int m0 = mt * 128;
    uint32_t sA = (uint32_t)__cvta_generic_to_shared(sm);
    uint32_t sB = sA + 32768;
    int warp = tid >> 5, lane = tid & 31, wm = warp >> 1, wn = warp & 1;
    int g = lane >> 2, t4 = lane & 3;

    const char* aTile = reinterpret_cast<const char*>(g_adjh) +
                        ((size_t)(b * 32 + mt)) * 64 * 16384;
    const char* zTile = reinterpret_cast<const char*>(mode == 1 ? g_z1 : g_z2) +
                        (size_t)b * 64 * 8192;

    if (tid == 0) {
#pragma unroll
        for (int s = 0; s < 2; s++) {
            mbar_expect(mF + s * 8, 24576);
            bulk_g2s(sA + s * 16384, aTile + (size_t)s * 16384, 16384, mF + s * 8);
            bulk_g2s(sB + s * 8192,  zTile + (size_t)s * 8192,  8192,  mF + s * 8);
        }
    }

    float acc[2][4][4];
#pragma unroll
    for (int mti = 0; mti < 2; mti++)
#pragma unroll
        for (int nt = 0; nt < 4; nt++)
#pragma unroll
            for (int c = 0; c < 4; c++) acc[mti][nt][c] = 0.f;

    for (int kb = 0; kb < 64; kb++) {
        int buf = kb & 1;
        uint32_t par = (kb >> 1) & 1;
        mbar_wait(mF + buf * 8, par);
        uint32_t Ab = sA + buf * 16384, Bb = sB + buf * 8192;
#pragma unroll
        for (int kt = 0; kt < 4; kt++) {
            uint32_t a[2][4], bb[4][2];
            int chunk = kt * 2 + (lane >> 4);
#pragma unroll
            for (int mti = 0; mti < 2; mti++) {
                int row = wm * 32 + mti * 16 + (lane & 15);
                ldm4(a[mti][0], a[mti][1], a[mti][2], a[mti][3],
                     Ab + row * 128 + ((chunk ^ (row & 7)) << 4));
            }
#pragma unroll
            for (int pr = 0; pr < 2; pr++) {
                int rn = wn * 32 + pr * 16 + (lane & 15);
                uint32_t r0, r1, r2, r3;
                ldm4(r0, r1, r2, r3, Bb + rn * 128 + ((chunk ^ (rn & 7)) << 4));
                bb[pr * 2][0] = r0; bb[pr * 2 + 1][0] = r1;
                bb[pr * 2][1] = r2; bb[pr * 2 + 1][1] = r3;
            }
#pragma unroll
            for (int mti = 0; mti < 2; mti++)
#pragma unroll
                for (int nt = 0; nt < 4; nt++) mma16816(acc[mti][nt], a[mti], bb[nt]);
        }
        __syncthreads();
        if (tid == 0 && kb + 2 < 64) {
            mbar_expect(mF + buf * 8, 24576);
            bulk_g2s(sA + buf * 16384, aTile + (size_t)(kb + 2) * 16384, 16384, mF + buf * 8);
            bulk_g2s(sB + buf * 8192,  zTile + (size_t)(kb + 2) * 8192,  8192,  mF + buf * 8);
        }
    }

    if (mode == 1) {
        load_wT(Wnext, sm + 40960, tid);
#pragma unroll
        for (int mti = 0; mti < 2; mti++)
#pragma unroll
            for (int h2 = 0; h2 < 2; h2++) {
                int row = wm * 32 + mti * 16 + g + h2 * 8;
                float dv = __ldcg(&g_dis[b * NN + m0 + row]);
#pragma unroll
                for (int nt = 0; nt < 4; nt++) {
                    int col = wn * 32 + nt * 8 + t4 * 2;
                    float v0 = fmaxf(acc[mti][nt][h2 * 2]     + bias[col],     0.f) * dv;
                    float v1 = fmaxf(acc[mti][nt][h2 * 2 + 1] + bias[col + 1], 0.f) * dv;
                    int chunk = col >> 3;
                    int off = row * 128 + ((chunk ^ (row & 7)) << 4) + (col & 7) * 2;
                    __half2 p = __floats2half2_rn(v0, v1);
                    *reinterpret_cast<uint32_t*>(sm + off) = *reinterpret_cast<uint32_t*>(&p);
                }
            }
        __syncthreads();
        __half* zs = reinterpret_cast<__half*>(sm + 16384);
        mini_mma_store(sA, sA + 40960, zs, wm, wn, lane);
        __syncthreads();
        for (int idx = tid; idx < 4096; idx += 256) {
            int d = idx >> 6, cw = idx & 63;
            uint32_t v = *reinterpret_cast<uint32_t*>(zs + d * 136 + cw * 2);
            store_z_tiled(g_z2, b, d, m0 + cw * 2, v);
        }
        __syncthreads();
        __threadfence();
        if (tid == 0) atomicAdd(&g_g1Done[b], 1u);
    } else {
        float* hs = reinterpret_cast<float*>(sm);
#pragma unroll
        for (int mti = 0; mti < 2; mti++)
#pragma unroll
            for (int h2 = 0; h2 < 2; h2++) {
                int row = wm * 32 + mti * 16 + g + h2 * 8;
#pragma unroll
                for (int nt = 0; nt < 4; nt++) {
                    int col = wn * 32 + nt * 8 + t4 * 2;
                    hs[row * 65 + col]     = fmaxf(acc[mti][nt][h2 * 2]     + bias[col],     0.f);
                    hs[row * 65 + col + 1] = fmaxf(acc[mti][nt][h2 * 2 + 1] + bias[col + 1], 0.f);
                }
            }
        __syncthreads();
        float* red = reinterpret_cast<float*>(sm + 33792);
        int d = tid & 63, part = tid >> 6;
        float s = 0.f, mx = -1e30f;
#pragma unroll 4
        for (int r = part * 32; r < part * 32 + 32; r++) {
            float v = hs[r * 65 + d];
            s += v; mx = fmaxf(mx, v);
        }
        red[tid] = s; red[256 + tid] = mx;
        __syncthreads();
        if (tid < 64) {
            float S = red[tid] + red[tid + 64] + red[tid + 128] + red[tid + 192];
            float M = fmaxf(fmaxf(red[256 + tid], red[256 + tid + 64]),
                            fmaxf(red[256 + tid + 128], red[256 + tid + 192]));
            g_pool[((b * 32 + mt) << 7) + tid]      = S;
            g_pool[((b * 32 + mt) << 7) + 64 + tid] = M;
        }
        __syncthreads();
    }
}

// ---------------- persistent dataflow mega-kernel ----------------------------
__global__ void __launch_bounds__(256, 4) mega(
    const int* __restrict__ ntypes, const int* __restrict__ nlabels,
    const float* __restrict__ adj,
    const float* __restrict__ te, const float* __restrict__ le,
    const float* __restrict__ W1, const float* __restrict__ b1v,
    const float* __restrict__ W2, const float* __restrict__ b2v) {
    extern __shared__ char sm[];
    __shared__ __align__(8) uint64_t mbF[2];
    __shared__ int s_kind;
    __shared__ unsigned s_task;
    __shared__ unsigned s_st;
    int tid = threadIdx.x;
    uint32_t mF = (uint32_t)__cvta_generic_to_shared(mbF);
    if (tid == 0) { mbar_init(mF, 1); mbar_init(mF + 8, 1); }
    __syncthreads();

    for (;;) {
        if (tid == 0) {
            int kind = -1; unsigned task = 0;
            unsigned h = atomicAdd(&g_q2, 0u);                  // peek
            if (h < 512u && atomicAdd(&g_g1Done[h >> 5], 0u) >= 32u) {
                unsigned t = atomicAdd(&g_q2, 1u);
                if (t < 512u) { kind = 2; task = t; }
            }
            if (kind < 0) {
                h = atomicAdd(&g_q1, 0u);
                if (h < 512u && atomicAdd(&g_convDone[h >> 5], 0u) >= 64u) {
                    unsigned t = atomicAdd(&g_q1, 1u);
                    if (t < 512u) { kind = 1; task = t; }
                }
            }
            if (kind < 0) {
                unsigned t = atomicAdd(&g_qc, 1u);
                if (t < 1024u) { kind = 0; task = t; }
            }
            if (kind < 0) {
                unsigned t = atomicAdd(&g_q1, 1u);
                if (t < 512u) { kind = 1; task = t; }
                else {
                    t = atomicAdd(&g_q2, 1u);
                    if (t < 512u) { kind = 2; task = t; }
                    else kind = 3;
                }
            }
            s_kind = kind; s_task = task;
        }
        __syncthreads();
        int kind = s_kind; unsigned task = s_task;
        if (kind == 3) break;

        if (kind == 0) {
            do_conv(task, adj, ntypes, nlabels, te, le, W1, sm, tid);
        } else {
            int b = (int)(task >> 5), mt = (int)(task & 31);
            // readiness spin with conv-stealing (deadlock-free)
            for (;;) {
                if (tid == 0) {
                    unsigned tgt = (kind == 1) ? 64u : 32u;
                    unsigned* cnt = (kind == 1) ? &g_convDone[b] : &g_g1Done[b];
                    if (atomicAdd(cnt, 0u) >= tgt) s_st = 0xffffffffu;
                    else {
                        unsigned t = atomicAdd(&g_qc, 1u);
                        s_st = (t < 1024u) ? t : 0xfffffffeu;
                    }
                }
                __syncthreads();
                unsigned st = s_st;
                if (st == 0xffffffffu) break;
                if (st == 0xfffffffeu) {
                    if (tid == 0) __nanosleep(256);
                    __syncthreads();
                    continue;
                }
                do_conv(st, adj, ntypes, nlabels, te, le, W1, sm, tid);
                __syncthreads();
            }
            do_gemm(kind, b, mt, (kind == 1) ? b1v : b2v, W2, sm, tid, mF);
        }
        __syncthreads();
    }
}

// ---------------- final combine + readout + counter reset --------------------
__global__ void final_kernel(const float* __restrict__ Wr,
                             const float* __restrict__ br,
                             float* __restrict__ out) {
    int b = blockIdx.x, t = threadIdx.x;
    __shared__ float pooled[128];
    if (t < 64) {
        float s = 0.f;
        for (int c = 0; c < 32; c++) s += g_pool[((b * 32 + c) << 7) + t];
        pooled[t] = s * (1.0f / 4096.0f);
    } else {
        float m = -1e30f;
        for (int c = 0; c < 32; c++) m = fmaxf(m, g_pool[((b * 32 + c) << 7) + (t - 64) + 64]);
        pooled[t] = m;
    }
    __syncthreads();
    if (t < 64) {
        float acc = br[t];
#pragma unroll
        for (int j = 0; j < 128; j++) acc += pooled[j] * Wr[t * 128 + j];
        out[b * 64 + t] = acc;
    }
    if (t == 0) {                       // reset dataflow state for next replay
        g_convDone[b] = 0;
        g_g1Done[b] = 0;
        if (b == 0) { g_qc = 0; g_q1 = 0; g_q2 = 0; }
    }
}

// ---------------- launch -----------------------------------------------------
extern "C" void kernel_launch(void* const* d_in, const int* in_sizes, int n_in,
                              void* d_out, int out_size) {
    const int*   node_types  = (const int*)  d_in[0];
    const int*   node_labels = (const int*)  d_in[1];
    const float* adj         = (const float*)d_in[2];
    const float* type_emb    = (const float*)d_in[3];
    const float* label_emb   = (const float*)d_in[4];
    const float* W1          = (const float*)d_in[5];
    const float* b1          = (const float*)d_in[6];
    const float* W2          = (const float*)d_in[7];
    const float* b2          = (const float*)d_in[8];
    const float* Wr          = (const float*)d_in[9];
    const float* br          = (const float*)d_in[10];
    float* out = (float*)d_out;

    cudaFuncSetAttribute(mega, cudaFuncAttributeMaxDynamicSharedMemorySize, 49152);

    mega<<<512, 256, 49152>>>(node_types, node_labels, adj, type_emb, label_emb,
                              W1, b1, W2, b2);
    final_kernel<<<BB, 128>>>(Wr, br, out);
}